// round 1
// baseline (speedup 1.0000x reference)
#include <cuda_runtime.h>
#include <math.h>

#define NROWS 4096
#define DIM   512
#define BM    128
#define BK    16
#define NT    (NROWS / BM)   // 32 tiles per dimension

// Precomputed squared row norms (scratch via __device__ global — no allocs allowed).
__device__ float g_sq[NROWS];

// ---------------------------------------------------------------------------
// Kernel 1: squared norm of each row. 4096 blocks × 128 threads.
// ---------------------------------------------------------------------------
__global__ void row_sqnorm_kernel(const float* __restrict__ x) {
    int row = blockIdx.x;
    const float4* xr = (const float4*)(x + (size_t)row * DIM);
    float s = 0.0f;
    for (int c = threadIdx.x; c < DIM / 4; c += blockDim.x) {
        float4 v = xr[c];
        s += v.x * v.x + v.y * v.y + v.z * v.z + v.w * v.w;
    }
    #pragma unroll
    for (int o = 16; o > 0; o >>= 1)
        s += __shfl_xor_sync(0xffffffff, s, o);
    __shared__ float red[4];
    if ((threadIdx.x & 31) == 0) red[threadIdx.x >> 5] = s;
    __syncthreads();
    if (threadIdx.x == 0)
        g_sq[row] = red[0] + red[1] + red[2] + red[3];
}

// ---------------------------------------------------------------------------
// Kernel 2: one block per lower-triangle 128x128 tile pair (ti >= tj).
// Computes the Gram tile via register-tiled fp32 FFMA, then
// d(i,j) = sqrt(max(sq[i] + sq[j] - 2*dot, 0)) written at i*(i-1)/2 + j.
// ---------------------------------------------------------------------------
__global__ __launch_bounds__(256, 2)
void pdist_tile_kernel(const float* __restrict__ x, float* __restrict__ out) {
    // Map linear block id -> (ti, tj), ti >= tj, bid = ti*(ti+1)/2 + tj
    int bid = blockIdx.x;
    int ti = (int)((sqrtf(8.0f * (float)bid + 1.0f) - 1.0f) * 0.5f);
    while ((ti + 1) * (ti + 2) / 2 <= bid) ti++;
    while (ti * (ti + 1) / 2 > bid) ti--;
    int tj = bid - ti * (ti + 1) / 2;

    const int i0 = ti * BM;
    const int j0 = tj * BM;

    __shared__ float As[BK][BM];   // As[k][m] = x[i0+m][k0+k]
    __shared__ float Bs[BK][BM];   // Bs[k][n] = x[j0+n][k0+k]

    const int tid = threadIdx.x;
    const int tn  = tid & 15;        // 0..15 -> columns (j)
    const int tm  = tid >> 4;        // 0..15 -> rows (i)

    float acc[8][8];
    #pragma unroll
    for (int a = 0; a < 8; a++)
        #pragma unroll
        for (int b = 0; b < 8; b++)
            acc[a][b] = 0.0f;

    for (int k0 = 0; k0 < DIM; k0 += BK) {
        // Stage loads: 128 rows x 16 k = 512 float4 per matrix; 2 per thread.
        // Mapping: l in {tid, tid+256}; c4 = l>>7 (which float4 along k),
        // r = l&127 (row). Warp => 32 distinct r at fixed k -> STS conflict-free.
        #pragma unroll
        for (int l = tid; l < 512; l += 256) {
            int c4 = l >> 7;       // 0..3
            int r  = l & 127;
            int kk = k0 + c4 * 4;
            float4 va = *(const float4*)(x + (size_t)(i0 + r) * DIM + kk);
            As[c4 * 4 + 0][r] = va.x;
            As[c4 * 4 + 1][r] = va.y;
            As[c4 * 4 + 2][r] = va.z;
            As[c4 * 4 + 3][r] = va.w;
            float4 vb = *(const float4*)(x + (size_t)(j0 + r) * DIM + kk);
            Bs[c4 * 4 + 0][r] = vb.x;
            Bs[c4 * 4 + 1][r] = vb.y;
            Bs[c4 * 4 + 2][r] = vb.z;
            Bs[c4 * 4 + 3][r] = vb.w;
        }
        __syncthreads();

        #pragma unroll
        for (int k = 0; k < BK; k++) {
            float a[8], b[8];
            *(float4*)(a)     = *(const float4*)&As[k][tm * 8];
            *(float4*)(a + 4) = *(const float4*)&As[k][tm * 8 + 4];
            *(float4*)(b)     = *(const float4*)&Bs[k][tn * 8];
            *(float4*)(b + 4) = *(const float4*)&Bs[k][tn * 8 + 4];
            #pragma unroll
            for (int mi = 0; mi < 8; mi++)
                #pragma unroll
                for (int ni = 0; ni < 8; ni++)
                    acc[mi][ni] = fmaf(a[mi], b[ni], acc[mi][ni]);
        }
        __syncthreads();
    }

    // Epilogue: d2 = sq[i] + sq[j] - 2*dot; flat index i*(i-1)/2 + j (i > j).
    float sj[8];
    #pragma unroll
    for (int ni = 0; ni < 8; ni++)
        sj[ni] = g_sq[j0 + tn * 8 + ni];

    #pragma unroll
    for (int mi = 0; mi < 8; mi++) {
        int i = i0 + tm * 8 + mi;
        float si = g_sq[i];
        unsigned base = (unsigned)(i * (i - 1) / 2);
        #pragma unroll
        for (int ni = 0; ni < 8; ni++) {
            int j = j0 + tn * 8 + ni;
            if (j < i) {
                float d2 = si + sj[ni] - 2.0f * acc[mi][ni];
                out[base + j] = sqrtf(fmaxf(d2, 0.0f));
            }
        }
    }
}

extern "C" void kernel_launch(void* const* d_in, const int* in_sizes, int n_in,
                              void* d_out, int out_size) {
    const float* x = (const float*)d_in[0];
    float* out = (float*)d_out;

    row_sqnorm_kernel<<<NROWS, 128>>>(x);

    const int nblocks = NT * (NT + 1) / 2;   // 528
    pdist_tile_kernel<<<nblocks, 256>>>(x, out);
}

// round 4
// speedup vs baseline: 3.0408x; 3.0408x over previous
#include <cuda_runtime.h>
#include <cstdint>
#include <math.h>

#define NROWS 4096
#define DIM   512
#define BM    128
#define BK    16
#define NT    (NROWS / BM)        // 32
#define NITER (DIM / BK)          // 32
#define SPAD  20                  // smem row stride in floats (16 + 4 pad)

__device__ float g_sq[NROWS];
__device__ float g_xr[NROWS * DIM];   // tf32-rounded copy of x (8 MB scratch)

__device__ __forceinline__ uint32_t smem_u32(const void* p) {
    uint32_t a;
    asm("{ .reg .u64 t; cvta.to.shared.u64 t, %1; cvt.u32.u64 %0, t; }"
        : "=r"(a) : "l"(p));
    return a;
}

__device__ __forceinline__ float tf32r(float v) {
    uint32_t r;
    asm("cvt.rna.tf32.f32 %0, %1;" : "=r"(r) : "f"(v));
    return __uint_as_float(r);
}

__device__ __forceinline__ void mma1688(float* d, const uint32_t* a, const uint32_t* b) {
    asm volatile(
        "mma.sync.aligned.m16n8k8.row.col.f32.tf32.tf32.f32 "
        "{%0,%1,%2,%3}, {%4,%5,%6,%7}, {%8,%9}, {%0,%1,%2,%3};"
        : "+f"(d[0]), "+f"(d[1]), "+f"(d[2]), "+f"(d[3])
        : "r"(a[0]), "r"(a[1]), "r"(a[2]), "r"(a[3]), "r"(b[0]), "r"(b[1]));
}

// ---------------------------------------------------------------------------
// Kernel 1: per-row squared norms (full fp32) + tf32-rounded copy of x.
// One warp per row.
// ---------------------------------------------------------------------------
__global__ void prep_kernel(const float* __restrict__ x) {
    int row  = blockIdx.x * (blockDim.x >> 5) + (threadIdx.x >> 5);
    int lane = threadIdx.x & 31;
    const float4* xr = (const float4*)(x + (size_t)row * DIM);
    float4* dr = (float4*)(g_xr + (size_t)row * DIM);
    float s = 0.0f;
    #pragma unroll
    for (int t = 0; t < 4; t++) {
        float4 v = xr[lane + t * 32];
        s += v.x * v.x + v.y * v.y + v.z * v.z + v.w * v.w;
        float4 o;
        o.x = tf32r(v.x); o.y = tf32r(v.y); o.z = tf32r(v.z); o.w = tf32r(v.w);
        dr[lane + t * 32] = o;
    }
    #pragma unroll
    for (int o = 16; o > 0; o >>= 1) s += __shfl_xor_sync(0xffffffffu, s, o);
    if (lane == 0) g_sq[row] = s;
}

// ---------------------------------------------------------------------------
// Kernel 2: Gram tile via mma.sync tf32, distance epilogue with direct stores.
// ---------------------------------------------------------------------------
__shared__ float As[2][BM][SPAD];
__shared__ float Bs[2][BM][SPAD];
__shared__ float sis[BM];
__shared__ float sjs[BM];

__device__ __forceinline__ void stage_tile(const float* __restrict__ src0,
                                           int row0, int k0,
                                           float (*dst)[SPAD], int tid) {
    #pragma unroll
    for (int h = 0; h < 2; h++) {
        int e   = tid + h * 256;
        int row = e >> 2;
        int seg = e & 3;
        const float* g = src0 + (size_t)(row0 + row) * DIM + k0 + seg * 4;
        uint32_t d = smem_u32(&dst[row][seg * 4]);
        asm volatile("cp.async.cg.shared.global [%0], [%1], 16;"
                     :: "r"(d), "l"(g) : "memory");
    }
}

__global__ __launch_bounds__(256, 2)
void pdist_mma_kernel(float* __restrict__ out) {
    const int tid  = threadIdx.x;
    const int wid  = tid >> 5;
    const int lane = tid & 31;
    const int g    = lane >> 2;      // fragment row group 0..7
    const int t    = lane & 3;       // fragment col group 0..3
    const int wm   = (wid >> 2) * 64;  // warp m offset (0 / 64)
    const int wn   = (wid & 3) * 32;   // warp n offset (0/32/64/96)

    // block -> lower-triangle tile pair (ti >= tj)
    int bid = blockIdx.x;
    int ti = (int)((sqrtf(8.0f * (float)bid + 1.0f) - 1.0f) * 0.5f);
    if (ti < 0) ti = 0;
    if (ti > NT - 1) ti = NT - 1;
    while (ti + 1 < NT && (ti + 1) * (ti + 2) / 2 <= bid) ti++;
    while (ti > 0 && ti * (ti + 1) / 2 > bid) ti--;
    int tj = bid - ti * (ti + 1) / 2;
    const int i0 = ti * BM, j0 = tj * BM;

    if (tid < BM) { sis[tid] = g_sq[i0 + tid]; sjs[tid] = g_sq[j0 + tid]; }

    float acc[4][4][4];
    #pragma unroll
    for (int a = 0; a < 4; a++)
        #pragma unroll
        for (int b = 0; b < 4; b++)
            #pragma unroll
            for (int c = 0; c < 4; c++)
                acc[a][b][c] = 0.0f;

    // prologue
    stage_tile(g_xr, i0, 0, As[0], tid);
    stage_tile(g_xr, j0, 0, Bs[0], tid);
    asm volatile("cp.async.commit_group;" ::: "memory");

    for (int c = 0; c < NITER; c++) {
        const int b = c & 1;
        if (c + 1 < NITER) {
            stage_tile(g_xr, i0, (c + 1) * BK, As[b ^ 1], tid);
            stage_tile(g_xr, j0, (c + 1) * BK, Bs[b ^ 1], tid);
            asm volatile("cp.async.commit_group;" ::: "memory");
            asm volatile("cp.async.wait_group 1;"  ::: "memory");
        } else {
            asm volatile("cp.async.wait_group 0;"  ::: "memory");
        }
        __syncthreads();

        #pragma unroll
        for (int ks = 0; ks < 2; ks++) {
            const int k8 = ks * 8;
            uint32_t af[4][4], bf[4][2];
            #pragma unroll
            for (int mi = 0; mi < 4; mi++) {
                int r = wm + mi * 16 + g;
                af[mi][0] = __float_as_uint(As[b][r    ][k8 + t]);
                af[mi][1] = __float_as_uint(As[b][r + 8][k8 + t]);
                af[mi][2] = __float_as_uint(As[b][r    ][k8 + t + 4]);
                af[mi][3] = __float_as_uint(As[b][r + 8][k8 + t + 4]);
            }
            #pragma unroll
            for (int ni = 0; ni < 4; ni++) {
                int r = wn + ni * 8 + g;
                bf[ni][0] = __float_as_uint(Bs[b][r][k8 + t]);
                bf[ni][1] = __float_as_uint(Bs[b][r][k8 + t + 4]);
            }
            #pragma unroll
            for (int mi = 0; mi < 4; mi++)
                #pragma unroll
                for (int ni = 0; ni < 4; ni++)
                    mma1688(acc[mi][ni], af[mi], bf[ni]);
        }
        __syncthreads();
    }

    // epilogue: d = sqrt(max(si + sj - 2*dot, 0)), out[i*(i-1)/2 + j], i > j
    const bool full = (ti != tj);
    #pragma unroll
    for (int mi = 0; mi < 4; mi++) {
        #pragma unroll
        for (int rr = 0; rr < 2; rr++) {
            int il = wm + mi * 16 + g + rr * 8;      // local i
            int i  = i0 + il;
            float si = sis[il];
            unsigned base = (unsigned)i * (unsigned)(i - 1) / 2u;
            #pragma unroll
            for (int ni = 0; ni < 4; ni++) {
                #pragma unroll
                for (int cc = 0; cc < 2; cc++) {
                    int jl = wn + ni * 8 + 2 * t + cc;  // local j
                    int j  = j0 + jl;
                    if (full || j < i) {
                        float d2 = si + sjs[jl] - 2.0f * acc[mi][ni][rr * 2 + cc];
                        out[base + (unsigned)j] = sqrtf(fmaxf(d2, 0.0f));
                    }
                }
            }
        }
    }
}

extern "C" void kernel_launch(void* const* d_in, const int* in_sizes, int n_in,
                              void* d_out, int out_size) {
    const float* x = (const float*)d_in[0];
    float* out = (float*)d_out;

    prep_kernel<<<NROWS / 8, 256>>>(x);

    const int nblocks = NT * (NT + 1) / 2;   // 528
    pdist_mma_kernel<<<nblocks, 256>>>(out);
}

// round 5
// speedup vs baseline: 3.2944x; 1.0834x over previous
#include <cuda_runtime.h>
#include <cstdint>
#include <math.h>

#define NROWS 4096
#define DIM   512
#define BM    128
#define BK    16
#define NT    (NROWS / BM)        // 32
#define NITER (DIM / BK)          // 32
#define SPAD  20                  // smem row stride in floats (16 + 4 pad)
#define NSTG  3                   // pipeline stages
#define STGF  (BM * SPAD)         // floats per stage per matrix (2560)

// dynamic smem layout (floats): As[3][128][20] | Bs[3][128][20] | sis[128] | sjs[128]
#define SM_AS   0
#define SM_BS   (NSTG * STGF)
#define SM_SIS  (2 * NSTG * STGF)
#define SM_SJS  (SM_SIS + BM)
#define SMEM_BYTES ((SM_SJS + BM) * 4)

__device__ float g_sq[NROWS];
__device__ float g_xr[NROWS * DIM];   // tf32-rounded copy of x (8 MB scratch)

__device__ __forceinline__ uint32_t smem_u32(const void* p) {
    uint32_t a;
    asm("{ .reg .u64 t; cvta.to.shared.u64 t, %1; cvt.u32.u64 %0, t; }"
        : "=r"(a) : "l"(p));
    return a;
}

__device__ __forceinline__ float tf32r(float v) {
    uint32_t r;
    asm("cvt.rna.tf32.f32 %0, %1;" : "=r"(r) : "f"(v));
    return __uint_as_float(r);
}

__device__ __forceinline__ void mma1688(float* d, const uint32_t* a, const uint32_t* b) {
    asm volatile(
        "mma.sync.aligned.m16n8k8.row.col.f32.tf32.tf32.f32 "
        "{%0,%1,%2,%3}, {%4,%5,%6,%7}, {%8,%9}, {%0,%1,%2,%3};"
        : "+f"(d[0]), "+f"(d[1]), "+f"(d[2]), "+f"(d[3])
        : "r"(a[0]), "r"(a[1]), "r"(a[2]), "r"(a[3]), "r"(b[0]), "r"(b[1]));
}

#define LDSM4(r0, r1, r2, r3, addr)                                             \
    asm volatile("ldmatrix.sync.aligned.m8n8.x4.shared.b16 {%0,%1,%2,%3}, [%4];"\
        : "=r"(r0), "=r"(r1), "=r"(r2), "=r"(r3) : "r"(addr))

// ---------------------------------------------------------------------------
// Kernel 1: per-row squared norms (full fp32) + tf32-rounded copy of x.
// ---------------------------------------------------------------------------
__global__ void prep_kernel(const float* __restrict__ x) {
    int row  = blockIdx.x * (blockDim.x >> 5) + (threadIdx.x >> 5);
    int lane = threadIdx.x & 31;
    const float4* xr = (const float4*)(x + (size_t)row * DIM);
    float4* dr = (float4*)(g_xr + (size_t)row * DIM);
    float s = 0.0f;
    #pragma unroll
    for (int t = 0; t < 4; t++) {
        float4 v = xr[lane + t * 32];
        s += v.x * v.x + v.y * v.y + v.z * v.z + v.w * v.w;
        float4 o;
        o.x = tf32r(v.x); o.y = tf32r(v.y); o.z = tf32r(v.z); o.w = tf32r(v.w);
        dr[lane + t * 32] = o;
    }
    #pragma unroll
    for (int o = 16; o > 0; o >>= 1) s += __shfl_xor_sync(0xffffffffu, s, o);
    if (lane == 0) g_sq[row] = s;
}

// ---------------------------------------------------------------------------
// Kernel 2: Gram tile via mma.sync tf32 + ldmatrix fragments, 3-stage cp.async.
// ---------------------------------------------------------------------------
__device__ __forceinline__ void stage_tile(const float* __restrict__ src0,
                                           int row0, int k0,
                                           float* dst, int tid) {
    #pragma unroll
    for (int h = 0; h < 2; h++) {
        int e   = tid + h * 256;
        int row = e >> 2;
        int seg = e & 3;
        const float* g = src0 + (size_t)(row0 + row) * DIM + k0 + seg * 4;
        uint32_t d = smem_u32(dst + row * SPAD + seg * 4);
        asm volatile("cp.async.cg.shared.global [%0], [%1], 16;"
                     :: "r"(d), "l"(g) : "memory");
    }
}

__global__ __launch_bounds__(256, 2)
void pdist_mma_kernel(float* __restrict__ out) {
    extern __shared__ float sm[];
    float* As  = sm + SM_AS;
    float* Bs  = sm + SM_BS;
    float* sis = sm + SM_SIS;
    float* sjs = sm + SM_SJS;

    const int tid  = threadIdx.x;
    const int wid  = tid >> 5;
    const int lane = tid & 31;
    const int g    = lane >> 2;        // fragment row group 0..7
    const int t    = lane & 3;         // fragment col group 0..3
    const int wm   = (wid >> 2) * 64;  // warp m offset (0 / 64)
    const int wn   = (wid & 3) * 32;   // warp n offset (0/32/64/96)

    // block -> lower-triangle tile pair (ti >= tj)
    int bid = blockIdx.x;
    int ti = (int)((sqrtf(8.0f * (float)bid + 1.0f) - 1.0f) * 0.5f);
    if (ti < 0) ti = 0;
    if (ti > NT - 1) ti = NT - 1;
    while (ti + 1 < NT && (ti + 1) * (ti + 2) / 2 <= bid) ti++;
    while (ti > 0 && ti * (ti + 1) / 2 > bid) ti--;
    int tj = bid - ti * (ti + 1) / 2;
    const int i0 = ti * BM, j0 = tj * BM;

    if (tid < BM) { sis[tid] = g_sq[i0 + tid]; sjs[tid] = g_sq[j0 + tid]; }

    // ldmatrix source addresses (lane-dependent), stage 0:
    // A x4: m0 rows 0-7 k0-3 | m1 rows 8-15 k0-3 | m2 rows 0-7 k4-7 | m3 rows 8-15 k4-7
    const uint32_t a_base =
        smem_u32(As + (wm + (lane & 15)) * SPAD + ((lane >> 4) << 2));
    // B x4: m0 rows(ni) k0-3 | m1 rows(ni) k4-7 | m2 rows(ni+1) k0-3 | m3 rows(ni+1) k4-7
    const uint32_t b_base =
        smem_u32(Bs + (wn + (lane & 7) + ((lane >> 4) << 3)) * SPAD +
                 (((lane >> 3) & 1) << 2));

    float acc[4][4][4];
    #pragma unroll
    for (int a = 0; a < 4; a++)
        #pragma unroll
        for (int b = 0; b < 4; b++)
            #pragma unroll
            for (int c = 0; c < 4; c++)
                acc[a][b][c] = 0.0f;

    // prologue: stages 0,1
    #pragma unroll
    for (int p = 0; p < 2; p++) {
        stage_tile(g_xr, i0, p * BK, As + p * STGF, tid);
        stage_tile(g_xr, j0, p * BK, Bs + p * STGF, tid);
        asm volatile("cp.async.commit_group;" ::: "memory");
    }

    for (int c = 0; c < NITER; c++) {
        const int s = c % NSTG;
        if (c + 2 < NITER) {
            const int ns = (c + 2) % NSTG;
            stage_tile(g_xr, i0, (c + 2) * BK, As + ns * STGF, tid);
            stage_tile(g_xr, j0, (c + 2) * BK, Bs + ns * STGF, tid);
            asm volatile("cp.async.commit_group;" ::: "memory");
            asm volatile("cp.async.wait_group 2;" ::: "memory");
        } else if (c + 1 < NITER) {
            asm volatile("cp.async.wait_group 1;" ::: "memory");
        } else {
            asm volatile("cp.async.wait_group 0;" ::: "memory");
        }
        __syncthreads();

        const uint32_t soff = (uint32_t)(s * STGF * 4);
        #pragma unroll
        for (int ks = 0; ks < 2; ks++) {
            const uint32_t ko = soff + (uint32_t)(ks * 32);   // +8 floats
            uint32_t bf[2][4];
            LDSM4(bf[0][0], bf[0][1], bf[0][2], bf[0][3], b_base + ko);
            LDSM4(bf[1][0], bf[1][1], bf[1][2], bf[1][3],
                  b_base + ko + 16 * SPAD * 4);
            #pragma unroll
            for (int mi = 0; mi < 4; mi++) {
                uint32_t af[4];
                LDSM4(af[0], af[1], af[2], af[3],
                      a_base + ko + (uint32_t)(mi * 16 * SPAD * 4));
                mma1688(acc[mi][0], af, &bf[0][0]);
                mma1688(acc[mi][1], af, &bf[0][2]);
                mma1688(acc[mi][2], af, &bf[1][0]);
                mma1688(acc[mi][3], af, &bf[1][2]);
            }
        }
        __syncthreads();
    }

    // epilogue: d = sqrt(max(si + sj - 2*dot, 0)), out[i*(i-1)/2 + j], i > j
    const bool full = (ti != tj);
    #pragma unroll
    for (int mi = 0; mi < 4; mi++) {
        #pragma unroll
        for (int rr = 0; rr < 2; rr++) {
            int il = wm + mi * 16 + g + rr * 8;      // local i
            int i  = i0 + il;
            float si = sis[il];
            unsigned base = (unsigned)i * (unsigned)(i - 1) / 2u;
            #pragma unroll
            for (int ni = 0; ni < 4; ni++) {
                #pragma unroll
                for (int cc = 0; cc < 2; cc++) {
                    int jl = wn + ni * 8 + 2 * t + cc;  // local j
                    int j  = j0 + jl;
                    if (full || j < i) {
                        float d2 = si + sjs[jl] - 2.0f * acc[mi][ni][rr * 2 + cc];
                        out[base + (unsigned)j] = sqrtf(fmaxf(d2, 0.0f));
                    }
                }
            }
        }
    }
}

extern "C" void kernel_launch(void* const* d_in, const int* in_sizes, int n_in,
                              void* d_out, int out_size) {
    const float* x = (const float*)d_in[0];
    float* out = (float*)d_out;

    cudaFuncSetAttribute(pdist_mma_kernel,
                         cudaFuncAttributeMaxDynamicSharedMemorySize, SMEM_BYTES);

    prep_kernel<<<NROWS / 8, 256>>>(x);

    const int nblocks = NT * (NT + 1) / 2;   // 528
    pdist_mma_kernel<<<nblocks, 256, SMEM_BYTES>>>(out);
}

// round 7
// speedup vs baseline: 3.5238x; 1.0697x over previous
#include <cuda_runtime.h>
#include <cstdint>
#include <math.h>

#define NROWS 4096
#define DIM   512
#define BM    128
#define BK    16
#define NT    (NROWS / BM)        // 32
#define NITER (DIM / BK)          // 32
#define SPAD  20                  // smem row stride in floats (16 + 4 pad)
#define NSTG  4                   // pipeline stages (single-barrier safe)
#define STGF  (BM * SPAD)         // floats per stage per matrix (2560)

// dynamic smem (floats): As[4][128][20] | Bs[4][128][20] | sis[128] | sjs[128]
#define SM_AS   0
#define SM_BS   (NSTG * STGF)
#define SM_SIS  (2 * NSTG * STGF)
#define SM_SJS  (SM_SIS + BM)
#define SMEM_BYTES ((SM_SJS + BM) * 4)

__device__ float g_sq[NROWS];
__device__ float g_xr[NROWS * DIM];   // tf32-rounded copy of x (8 MB scratch)

__device__ __forceinline__ uint32_t smem_u32(const void* p) {
    uint32_t a;
    asm("{ .reg .u64 t; cvta.to.shared.u64 t, %1; cvt.u32.u64 %0, t; }"
        : "=r"(a) : "l"(p));
    return a;
}

__device__ __forceinline__ float tf32r(float v) {
    uint32_t r;
    asm("cvt.rna.tf32.f32 %0, %1;" : "=r"(r) : "f"(v));
    return __uint_as_float(r);
}

__device__ __forceinline__ void mma1688(float* d, const uint32_t* a, const uint32_t* b) {
    asm volatile(
        "mma.sync.aligned.m16n8k8.row.col.f32.tf32.tf32.f32 "
        "{%0,%1,%2,%3}, {%4,%5,%6,%7}, {%8,%9}, {%0,%1,%2,%3};"
        : "+f"(d[0]), "+f"(d[1]), "+f"(d[2]), "+f"(d[3])
        : "r"(a[0]), "r"(a[1]), "r"(a[2]), "r"(a[3]), "r"(b[0]), "r"(b[1]));
}

#define LDSM4(r0, r1, r2, r3, addr)                                             \
    asm volatile("ldmatrix.sync.aligned.m8n8.x4.shared.b16 {%0,%1,%2,%3}, [%4];"\
        : "=r"(r0), "=r"(r1), "=r"(r2), "=r"(r3) : "r"(addr))

// ---------------------------------------------------------------------------
// Kernel 1: per-row squared norms (full fp32) + tf32-rounded copy of x.
// ---------------------------------------------------------------------------
__global__ void prep_kernel(const float* __restrict__ x) {
    int row  = blockIdx.x * (blockDim.x >> 5) + (threadIdx.x >> 5);
    int lane = threadIdx.x & 31;
    const float4* xr = (const float4*)(x + (size_t)row * DIM);
    float4* dr = (float4*)(g_xr + (size_t)row * DIM);
    float s = 0.0f;
    #pragma unroll
    for (int t = 0; t < 4; t++) {
        float4 v = xr[lane + t * 32];
        s += v.x * v.x + v.y * v.y + v.z * v.z + v.w * v.w;
        float4 o;
        o.x = tf32r(v.x); o.y = tf32r(v.y); o.z = tf32r(v.z); o.w = tf32r(v.w);
        dr[lane + t * 32] = o;
    }
    #pragma unroll
    for (int o = 16; o > 0; o >>= 1) s += __shfl_xor_sync(0xffffffffu, s, o);
    if (lane == 0) g_sq[row] = s;
}

// ---------------------------------------------------------------------------
// Kernel 2: Gram tile via mma.sync tf32 + ldmatrix, 4-stage / 1-barrier pipe.
// ---------------------------------------------------------------------------
__device__ __forceinline__ void stage_tile(const float* __restrict__ src0,
                                           int row0, int k0,
                                           float* dst, int tid) {
    #pragma unroll
    for (int h = 0; h < 2; h++) {
        int e   = tid + h * 256;
        int row = e >> 2;
        int seg = e & 3;
        const float* g = src0 + (size_t)(row0 + row) * DIM + k0 + seg * 4;
        uint32_t d = smem_u32(dst + row * SPAD + seg * 4);
        asm volatile("cp.async.cg.shared.global [%0], [%1], 16;"
                     :: "r"(d), "l"(g) : "memory");
    }
}

__global__ __launch_bounds__(256, 2)
void pdist_mma_kernel(float* __restrict__ out) {
    extern __shared__ float sm[];
    float* As  = sm + SM_AS;
    float* Bs  = sm + SM_BS;
    float* sis = sm + SM_SIS;
    float* sjs = sm + SM_SJS;

    const int tid  = threadIdx.x;
    const int wid  = tid >> 5;
    const int lane = tid & 31;
    const int g    = lane >> 2;        // fragment row group 0..7
    const int t    = lane & 3;         // fragment col group 0..3
    const int wm   = (wid >> 2) * 64;  // warp m offset (0 / 64)
    const int wn   = (wid & 3) * 32;   // warp n offset (0/32/64/96)

    // block -> lower-triangle tile pair (ti >= tj)
    int bid = blockIdx.x;
    int ti = (int)((sqrtf(8.0f * (float)bid + 1.0f) - 1.0f) * 0.5f);
    if (ti < 0) ti = 0;
    if (ti > NT - 1) ti = NT - 1;
    while (ti + 1 < NT && (ti + 1) * (ti + 2) / 2 <= bid) ti++;
    while (ti > 0 && ti * (ti + 1) / 2 > bid) ti--;
    int tj = bid - ti * (ti + 1) / 2;
    const int i0 = ti * BM, j0 = tj * BM;

    if (tid < BM) { sis[tid] = g_sq[i0 + tid]; sjs[tid] = g_sq[j0 + tid]; }

    // ldmatrix source addresses (lane-dependent), stage 0
    const uint32_t a_base =
        smem_u32(As + (wm + (lane & 15)) * SPAD + ((lane >> 4) << 2));
    const uint32_t b_base =
        smem_u32(Bs + (wn + (lane & 7) + ((lane >> 4) << 3)) * SPAD +
                 (((lane >> 3) & 1) << 2));

    float acc[4][4][4];
    #pragma unroll
    for (int a = 0; a < 4; a++)
        #pragma unroll
        for (int b = 0; b < 4; b++)
            #pragma unroll
            for (int c = 0; c < 4; c++)
                acc[a][b][c] = 0.0f;

    // prologue: stages 0,1
    #pragma unroll
    for (int p = 0; p < 2; p++) {
        stage_tile(g_xr, i0, p * BK, As + p * STGF, tid);
        stage_tile(g_xr, j0, p * BK, Bs + p * STGF, tid);
        asm volatile("cp.async.commit_group;" ::: "memory");
    }

    for (int c = 0; c < NITER; c++) {
        const int s = c & (NSTG - 1);
        if (c + 2 < NITER) {
            const int ns = (c + 2) & (NSTG - 1);
            stage_tile(g_xr, i0, (c + 2) * BK, As + ns * STGF, tid);
            stage_tile(g_xr, j0, (c + 2) * BK, Bs + ns * STGF, tid);
            asm volatile("cp.async.commit_group;" ::: "memory");
            asm volatile("cp.async.wait_group 2;" ::: "memory");
        } else if (c + 1 < NITER) {
            asm volatile("cp.async.wait_group 1;" ::: "memory");
        } else {
            asm volatile("cp.async.wait_group 0;" ::: "memory");
        }
        // Single barrier: orders this iteration's reads after all writes of
        // stage s, AND (for the writers of stage (c+2)&3) after every warp's
        // reads from iteration c-2, which the barrier at c-1 already ordered.
        __syncthreads();

        const uint32_t soff = (uint32_t)(s * STGF * 4);
        #pragma unroll
        for (int ks = 0; ks < 2; ks++) {
            const uint32_t ko = soff + (uint32_t)(ks * 32);   // +8 floats
            uint32_t bf[2][4];
            LDSM4(bf[0][0], bf[0][1], bf[0][2], bf[0][3], b_base + ko);
            LDSM4(bf[1][0], bf[1][1], bf[1][2], bf[1][3],
                  b_base + ko + 16 * SPAD * 4);
            #pragma unroll
            for (int mi = 0; mi < 4; mi++) {
                uint32_t af[4];
                LDSM4(af[0], af[1], af[2], af[3],
                      a_base + ko + (uint32_t)(mi * 16 * SPAD * 4));
                mma1688(acc[mi][0], af, &bf[0][0]);
                mma1688(acc[mi][1], af, &bf[0][2]);
                mma1688(acc[mi][2], af, &bf[1][0]);
                mma1688(acc[mi][3], af, &bf[1][2]);
            }
        }
    }

    // epilogue: d = sqrt(max(si + sj - 2*dot, 0)), out[i*(i-1)/2 + j], i > j
    if (ti != tj) {
        #pragma unroll
        for (int mi = 0; mi < 4; mi++)
            #pragma unroll
            for (int rr = 0; rr < 2; rr++) {
                int il = wm + mi * 16 + g + rr * 8;
                int i  = i0 + il;
                float si = sis[il];
                unsigned base = (unsigned)i * (unsigned)(i - 1) / 2u;
                #pragma unroll
                for (int ni = 0; ni < 4; ni++)
                    #pragma unroll
                    for (int cc = 0; cc < 2; cc++) {
                        int jl = wn + ni * 8 + 2 * t + cc;
                        float d2 = si + sjs[jl] - 2.0f * acc[mi][ni][rr * 2 + cc];
                        out[base + (unsigned)(j0 + jl)] = sqrtf(fmaxf(d2, 0.0f));
                    }
            }
    } else {
        #pragma unroll
        for (int mi = 0; mi < 4; mi++)
            #pragma unroll
            for (int rr = 0; rr < 2; rr++) {
                int il = wm + mi * 16 + g + rr * 8;
                int i  = i0 + il;
                float si = sis[il];
                unsigned base = (unsigned)i * (unsigned)(i - 1) / 2u;
                #pragma unroll
                for (int ni = 0; ni < 4; ni++)
                    #pragma unroll
                    for (int cc = 0; cc < 2; cc++) {
                        int jl = wn + ni * 8 + 2 * t + cc;
                        int j  = j0 + jl;
                        if (j < i) {
                            float d2 = si + sjs[jl] - 2.0f * acc[mi][ni][rr * 2 + cc];
                            out[base + (unsigned)j] = sqrtf(fmaxf(d2, 0.0f));
                        }
                    }
            }
    }
}

extern "C" void kernel_launch(void* const* d_in, const int* in_sizes, int n_in,
                              void* d_out, int out_size) {
    const float* x = (const float*)d_in[0];
    float* out = (float*)d_out;

    cudaFuncSetAttribute(pdist_mma_kernel,
                         cudaFuncAttributeMaxDynamicSharedMemorySize, SMEM_BYTES);

    prep_kernel<<<NROWS / 8, 256>>>(x);

    const int nblocks = NT * (NT + 1) / 2;   // 528
    pdist_mma_kernel<<<nblocks, 256, SMEM_BYTES>>>(out);
}

// round 8
// speedup vs baseline: 3.8364x; 1.0887x over previous
#include <cuda_runtime.h>
#include <cstdint>
#include <math.h>

#define NROWS 4096
#define DIM   512
#define BM    128
#define BK    32
#define NT    (NROWS / BM)        // 32
#define NITER (DIM / BK)          // 16
#define SPAD  36                  // smem row stride in floats (32 + 4 pad)
#define NSTG  2                   // double buffer, single barrier per iter
#define STGF  (BM * SPAD)         // floats per stage per matrix (4608)

// dynamic smem (floats): As[2][128][36] | Bs[2][128][36] | sis[128] | sjs[128]
#define SM_AS   0
#define SM_BS   (NSTG * STGF)
#define SM_SIS  (2 * NSTG * STGF)
#define SM_SJS  (SM_SIS + BM)
#define SMEM_BYTES ((SM_SJS + BM) * 4)

__device__ float g_sq[NROWS];
__device__ float g_xr[NROWS * DIM];   // tf32-rounded copy of x (8 MB scratch)

__device__ __forceinline__ uint32_t smem_u32(const void* p) {
    uint32_t a;
    asm("{ .reg .u64 t; cvta.to.shared.u64 t, %1; cvt.u32.u64 %0, t; }"
        : "=r"(a) : "l"(p));
    return a;
}

__device__ __forceinline__ float tf32r(float v) {
    uint32_t r;
    asm("cvt.rna.tf32.f32 %0, %1;" : "=r"(r) : "f"(v));
    return __uint_as_float(r);
}

__device__ __forceinline__ void mma1688(float* d, const uint32_t* a, const uint32_t* b) {
    asm volatile(
        "mma.sync.aligned.m16n8k8.row.col.f32.tf32.tf32.f32 "
        "{%0,%1,%2,%3}, {%4,%5,%6,%7}, {%8,%9}, {%0,%1,%2,%3};"
        : "+f"(d[0]), "+f"(d[1]), "+f"(d[2]), "+f"(d[3])
        : "r"(a[0]), "r"(a[1]), "r"(a[2]), "r"(a[3]), "r"(b[0]), "r"(b[1]));
}

#define LDSM4(r0, r1, r2, r3, addr)                                             \
    asm volatile("ldmatrix.sync.aligned.m8n8.x4.shared.b16 {%0,%1,%2,%3}, [%4];"\
        : "=r"(r0), "=r"(r1), "=r"(r2), "=r"(r3) : "r"(addr))

// ---------------------------------------------------------------------------
// Kernel 1: per-row squared norms (full fp32) + tf32-rounded copy of x.
// ---------------------------------------------------------------------------
__global__ void prep_kernel(const float* __restrict__ x) {
    int row  = blockIdx.x * (blockDim.x >> 5) + (threadIdx.x >> 5);
    int lane = threadIdx.x & 31;
    const float4* xr = (const float4*)(x + (size_t)row * DIM);
    float4* dr = (float4*)(g_xr + (size_t)row * DIM);
    float s = 0.0f;
    #pragma unroll
    for (int t = 0; t < 4; t++) {
        float4 v = xr[lane + t * 32];
        s += v.x * v.x + v.y * v.y + v.z * v.z + v.w * v.w;
        float4 o;
        o.x = tf32r(v.x); o.y = tf32r(v.y); o.z = tf32r(v.z); o.w = tf32r(v.w);
        dr[lane + t * 32] = o;
    }
    #pragma unroll
    for (int o = 16; o > 0; o >>= 1) s += __shfl_xor_sync(0xffffffffu, s, o);
    if (lane == 0) g_sq[row] = s;
}

// ---------------------------------------------------------------------------
// Kernel 2: Gram tile via mma.sync tf32 + ldmatrix, BK=32, 1 barrier/iter.
// ---------------------------------------------------------------------------
__device__ __forceinline__ void stage_tile(const float* __restrict__ src0,
                                           int row0, int k0,
                                           float* dst, int tid) {
    #pragma unroll
    for (int h = 0; h < 4; h++) {
        int e   = tid + h * 256;
        int row = e >> 3;          // 8 x 16B per row (BK=32 floats = 128B)
        int seg = e & 7;
        const float* g = src0 + (size_t)(row0 + row) * DIM + k0 + seg * 4;
        uint32_t d = smem_u32(dst + row * SPAD + seg * 4);
        asm volatile("cp.async.cg.shared.global [%0], [%1], 16;"
                     :: "r"(d), "l"(g) : "memory");
    }
}

__global__ __launch_bounds__(256, 2)
void pdist_mma_kernel(float* __restrict__ out) {
    extern __shared__ float sm[];
    float* As  = sm + SM_AS;
    float* Bs  = sm + SM_BS;
    float* sis = sm + SM_SIS;
    float* sjs = sm + SM_SJS;

    const int tid  = threadIdx.x;
    const int wid  = tid >> 5;
    const int lane = tid & 31;
    const int g    = lane >> 2;        // fragment row group 0..7
    const int t    = lane & 3;         // fragment col group 0..3
    const int wm   = (wid >> 2) * 64;  // warp m offset (0 / 64)
    const int wn   = (wid & 3) * 32;   // warp n offset (0/32/64/96)

    // block -> lower-triangle tile pair (ti >= tj)
    int bid = blockIdx.x;
    int ti = (int)((sqrtf(8.0f * (float)bid + 1.0f) - 1.0f) * 0.5f);
    if (ti < 0) ti = 0;
    if (ti > NT - 1) ti = NT - 1;
    while (ti + 1 < NT && (ti + 1) * (ti + 2) / 2 <= bid) ti++;
    while (ti > 0 && ti * (ti + 1) / 2 > bid) ti--;
    int tj = bid - ti * (ti + 1) / 2;
    const int i0 = ti * BM, j0 = tj * BM;

    if (tid < BM) { sis[tid] = g_sq[i0 + tid]; sjs[tid] = g_sq[j0 + tid]; }

    // ldmatrix source addresses (lane-dependent), stage 0
    const uint32_t a_base =
        smem_u32(As + (wm + (lane & 15)) * SPAD + ((lane >> 4) << 2));
    const uint32_t b_base =
        smem_u32(Bs + (wn + (lane & 7) + ((lane >> 4) << 3)) * SPAD +
                 (((lane >> 3) & 1) << 2));

    float acc[4][4][4];
    #pragma unroll
    for (int a = 0; a < 4; a++)
        #pragma unroll
        for (int b = 0; b < 4; b++)
            #pragma unroll
            for (int c = 0; c < 4; c++)
                acc[a][b][c] = 0.0f;

    // prologue: stage 0
    stage_tile(g_xr, i0, 0, As, tid);
    stage_tile(g_xr, j0, 0, Bs, tid);
    asm volatile("cp.async.commit_group;" ::: "memory");

    for (int c = 0; c < NITER; c++) {
        const int s = c & 1;
        // 1) complete all pending cp.async (stage s data)
        asm volatile("cp.async.wait_group 0;" ::: "memory");
        // 2) one barrier: orders every warp's reads of stage s^1 (iter c-1)
        //    before the prefetch writes below, and makes stage s visible.
        __syncthreads();
        // 3) prefetch next stage (safe: after the barrier)
        if (c + 1 < NITER) {
            const int ns = s ^ 1;
            stage_tile(g_xr, i0, (c + 1) * BK, As + ns * STGF, tid);
            stage_tile(g_xr, j0, (c + 1) * BK, Bs + ns * STGF, tid);
            asm volatile("cp.async.commit_group;" ::: "memory");
        }
        // 4) compute on stage s: 4 k8-slices, 64 MMAs
        const uint32_t soff = (uint32_t)(s * STGF * 4);
        #pragma unroll
        for (int ks = 0; ks < 4; ks++) {
            const uint32_t ko = soff + (uint32_t)(ks * 32);   // +8 floats
            uint32_t bf[2][4];
            LDSM4(bf[0][0], bf[0][1], bf[0][2], bf[0][3], b_base + ko);
            LDSM4(bf[1][0], bf[1][1], bf[1][2], bf[1][3],
                  b_base + ko + 16 * SPAD * 4);
            #pragma unroll
            for (int mi = 0; mi < 4; mi++) {
                uint32_t af[4];
                LDSM4(af[0], af[1], af[2], af[3],
                      a_base + ko + (uint32_t)(mi * 16 * SPAD * 4));
                mma1688(acc[mi][0], af, &bf[0][0]);
                mma1688(acc[mi][1], af, &bf[0][2]);
                mma1688(acc[mi][2], af, &bf[1][0]);
                mma1688(acc[mi][3], af, &bf[1][2]);
            }
        }
    }

    // epilogue: d = sqrt(max(si + sj - 2*dot, 0)), out[i*(i-1)/2 + j], i > j
    if (ti != tj) {
        #pragma unroll
        for (int mi = 0; mi < 4; mi++)
            #pragma unroll
            for (int rr = 0; rr < 2; rr++) {
                int il = wm + mi * 16 + g + rr * 8;
                int i  = i0 + il;
                float si = sis[il];
                unsigned base = (unsigned)i * (unsigned)(i - 1) / 2u;
                #pragma unroll
                for (int ni = 0; ni < 4; ni++)
                    #pragma unroll
                    for (int cc = 0; cc < 2; cc++) {
                        int jl = wn + ni * 8 + 2 * t + cc;
                        float d2 = si + sjs[jl] - 2.0f * acc[mi][ni][rr * 2 + cc];
                        out[base + (unsigned)(j0 + jl)] = sqrtf(fmaxf(d2, 0.0f));
                    }
            }
    } else {
        #pragma unroll
        for (int mi = 0; mi < 4; mi++)
            #pragma unroll
            for (int rr = 0; rr < 2; rr++) {
                int il = wm + mi * 16 + g + rr * 8;
                int i  = i0 + il;
                float si = sis[il];
                unsigned base = (unsigned)i * (unsigned)(i - 1) / 2u;
                #pragma unroll
                for (int ni = 0; ni < 4; ni++)
                    #pragma unroll
                    for (int cc = 0; cc < 2; cc++) {
                        int jl = wn + ni * 8 + 2 * t + cc;
                        int j  = j0 + jl;
                        if (j < i) {
                            float d2 = si + sjs[jl] - 2.0f * acc[mi][ni][rr * 2 + cc];
                            out[base + (unsigned)j] = sqrtf(fmaxf(d2, 0.0f));
                        }
                    }
            }
    }
}

extern "C" void kernel_launch(void* const* d_in, const int* in_sizes, int n_in,
                              void* d_out, int out_size) {
    const float* x = (const float*)d_in[0];
    float* out = (float*)d_out;

    cudaFuncSetAttribute(pdist_mma_kernel,
                         cudaFuncAttributeMaxDynamicSharedMemorySize, SMEM_BYTES);

    prep_kernel<<<NROWS / 8, 256>>>(x);

    const int nblocks = NT * (NT + 1) / 2;   // 528
    pdist_mma_kernel<<<nblocks, 256, SMEM_BYTES>>>(out);
}

// round 9
// speedup vs baseline: 3.9412x; 1.0273x over previous
#include <cuda_runtime.h>
#include <cuda_bf16.h>
#include <cstdint>
#include <math.h>

#define NROWS 4096
#define DIM   512
#define BM    128
#define BK    64                  // bf16 elements per k-iteration (128 B/row)
#define NT    (NROWS / BM)        // 32
#define NITER (DIM / BK)          // 8
#define SPAD  72                  // smem row stride in bf16 (64 + 8 pad = 144 B)
#define STGE  (BM * SPAD)         // bf16 elems per stage per matrix (9216)

// dynamic smem (bf16): As[2][128][72] | Bs[2][128][72] | sis[128]f32 | sjs[128]f32
#define SMEM_BYTES (4 * STGE * 2 + 2 * BM * 4)

__device__ float g_sq[NROWS];
__device__ __nv_bfloat16 g_xb[NROWS * DIM];   // bf16-rounded copy of x (4 MB)

__device__ __forceinline__ uint32_t smem_u32(const void* p) {
    uint32_t a;
    asm("{ .reg .u64 t; cvta.to.shared.u64 t, %1; cvt.u32.u64 %0, t; }"
        : "=r"(a) : "l"(p));
    return a;
}

__device__ __forceinline__ void mma16816(float* d, const uint32_t* a, const uint32_t* b) {
    asm volatile(
        "mma.sync.aligned.m16n8k16.row.col.f32.bf16.bf16.f32 "
        "{%0,%1,%2,%3}, {%4,%5,%6,%7}, {%8,%9}, {%0,%1,%2,%3};"
        : "+f"(d[0]), "+f"(d[1]), "+f"(d[2]), "+f"(d[3])
        : "r"(a[0]), "r"(a[1]), "r"(a[2]), "r"(a[3]), "r"(b[0]), "r"(b[1]));
}

#define LDSM4(r0, r1, r2, r3, addr)                                             \
    asm volatile("ldmatrix.sync.aligned.m8n8.x4.shared.b16 {%0,%1,%2,%3}, [%4];"\
        : "=r"(r0), "=r"(r1), "=r"(r2), "=r"(r3) : "r"(addr))

// ---------------------------------------------------------------------------
// Kernel 1: bf16-round x into g_xb; squared norms (fp32) of the ROUNDED data
// so the d^2 identity stays self-consistent. One warp per row.
// ---------------------------------------------------------------------------
__global__ void prep_kernel(const float* __restrict__ x) {
    int row  = blockIdx.x * (blockDim.x >> 5) + (threadIdx.x >> 5);
    int lane = threadIdx.x & 31;
    const float4* xr = (const float4*)(x + (size_t)row * DIM);
    uint2* dr = (uint2*)(g_xb + (size_t)row * DIM);
    float s = 0.0f;
    #pragma unroll
    for (int t = 0; t < 4; t++) {
        float4 v = xr[lane + t * 32];
        __nv_bfloat162 h0 = __floats2bfloat162_rn(v.x, v.y);
        __nv_bfloat162 h1 = __floats2bfloat162_rn(v.z, v.w);
        float a0 = __bfloat162float(h0.x), a1 = __bfloat162float(h0.y);
        float a2 = __bfloat162float(h1.x), a3 = __bfloat162float(h1.y);
        s += a0 * a0 + a1 * a1 + a2 * a2 + a3 * a3;
        uint2 o;
        o.x = *(uint32_t*)&h0; o.y = *(uint32_t*)&h1;
        dr[lane + t * 32] = o;
    }
    #pragma unroll
    for (int o = 16; o > 0; o >>= 1) s += __shfl_xor_sync(0xffffffffu, s, o);
    if (lane == 0) g_sq[row] = s;
}

// ---------------------------------------------------------------------------
// Kernel 2: Gram tile via mma.sync bf16 m16n8k16 + ldmatrix, 1 barrier/iter.
// ---------------------------------------------------------------------------
__device__ __forceinline__ void stage_tile(const __nv_bfloat16* __restrict__ src0,
                                           int row0, int k0,
                                           __nv_bfloat16* dst, int tid) {
    #pragma unroll
    for (int h = 0; h < 4; h++) {
        int e   = tid + h * 256;
        int row = e >> 3;          // 8 x 16B (8 bf16) chunks per 128B row
        int seg = e & 7;
        const __nv_bfloat16* g = src0 + (size_t)(row0 + row) * DIM + k0 + seg * 8;
        uint32_t d = smem_u32(dst + row * SPAD + seg * 8);
        asm volatile("cp.async.cg.shared.global [%0], [%1], 16;"
                     :: "r"(d), "l"(g) : "memory");
    }
}

__global__ __launch_bounds__(256, 2)
void pdist_mma_kernel(float* __restrict__ out) {
    extern __shared__ __nv_bfloat16 smb[];
    __nv_bfloat16* As = smb;
    __nv_bfloat16* Bs = smb + 2 * STGE;
    float* sis = (float*)(smb + 4 * STGE);
    float* sjs = sis + BM;

    const int tid  = threadIdx.x;
    const int wid  = tid >> 5;
    const int lane = tid & 31;
    const int g    = lane >> 2;        // acc row group 0..7
    const int t    = lane & 3;         // acc col group 0..3
    const int wm   = (wid >> 2) * 64;  // warp m offset (0 / 64)
    const int wn   = (wid & 3) * 32;   // warp n offset (0/32/64/96)

    // block -> lower-triangle tile pair (ti >= tj)
    int bid = blockIdx.x;
    int ti = (int)((sqrtf(8.0f * (float)bid + 1.0f) - 1.0f) * 0.5f);
    if (ti < 0) ti = 0;
    if (ti > NT - 1) ti = NT - 1;
    while (ti + 1 < NT && (ti + 1) * (ti + 2) / 2 <= bid) ti++;
    while (ti > 0 && ti * (ti + 1) / 2 > bid) ti--;
    int tj = bid - ti * (ti + 1) / 2;
    const int i0 = ti * BM, j0 = tj * BM;

    if (tid < BM) { sis[tid] = g_sq[i0 + tid]; sjs[tid] = g_sq[j0 + tid]; }

    // ldmatrix lane addresses (bf16 elems -> bytes via smem_u32 on typed ptr)
    // A x4 matrices: (rows 0-7,k0-7)(rows 8-15,k0-7)(rows 0-7,k8-15)(rows 8-15,k8-15)
    const uint32_t a_base = smem_u32(
        As + (wm + (((lane >> 3) & 1) << 3) + (lane & 7)) * SPAD + ((lane >> 4) << 3));
    // B x4 matrices: (n0-7,k0-7)(n0-7,k8-15)(n8-15,k0-7)(n8-15,k8-15)
    const uint32_t b_base = smem_u32(
        Bs + (wn + ((lane >> 4) << 3) + (lane & 7)) * SPAD + (((lane >> 3) & 1) << 3));

    float acc[4][4][4];
    #pragma unroll
    for (int a = 0; a < 4; a++)
        #pragma unroll
        for (int b = 0; b < 4; b++)
            #pragma unroll
            for (int c = 0; c < 4; c++)
                acc[a][b][c] = 0.0f;

    // prologue: stage 0
    stage_tile(g_xb, i0, 0, As, tid);
    stage_tile(g_xb, j0, 0, Bs, tid);
    asm volatile("cp.async.commit_group;" ::: "memory");

    for (int c = 0; c < NITER; c++) {
        const int s = c & 1;
        asm volatile("cp.async.wait_group 0;" ::: "memory");
        // one barrier: orders last iter's reads of stage s^1 before its
        // overwrite below, and makes stage s writes visible to all warps.
        __syncthreads();
        if (c + 1 < NITER) {
            const int ns = s ^ 1;
            stage_tile(g_xb, i0, (c + 1) * BK, As + ns * STGE, tid);
            stage_tile(g_xb, j0, (c + 1) * BK, Bs + ns * STGE, tid);
            asm volatile("cp.async.commit_group;" ::: "memory");
        }

        const uint32_t soff = (uint32_t)(s * STGE * 2);
        #pragma unroll
        for (int ks = 0; ks < 4; ks++) {
            const uint32_t ko = soff + (uint32_t)(ks * 32);   // +16 bf16
            uint32_t bregs[2][4];
            LDSM4(bregs[0][0], bregs[0][1], bregs[0][2], bregs[0][3], b_base + ko);
            LDSM4(bregs[1][0], bregs[1][1], bregs[1][2], bregs[1][3],
                  b_base + ko + 16 * SPAD * 2);
            #pragma unroll
            for (int mi = 0; mi < 4; mi++) {
                uint32_t af[4];
                LDSM4(af[0], af[1], af[2], af[3],
                      a_base + ko + (uint32_t)(mi * 16 * SPAD * 2));
                mma16816(acc[mi][0], af, &bregs[0][0]);
                mma16816(acc[mi][1], af, &bregs[0][2]);
                mma16816(acc[mi][2], af, &bregs[1][0]);
                mma16816(acc[mi][3], af, &bregs[1][2]);
            }
        }
    }

    // epilogue: d = sqrt(max(si + sj - 2*dot, 0)), out[i*(i-1)/2 + j], i > j
    if (ti != tj) {
        #pragma unroll
        for (int mi = 0; mi < 4; mi++)
            #pragma unroll
            for (int rr = 0; rr < 2; rr++) {
                int il = wm + mi * 16 + g + rr * 8;
                int i  = i0 + il;
                float si = sis[il];
                unsigned base = (unsigned)i * (unsigned)(i - 1) / 2u;
                #pragma unroll
                for (int ni = 0; ni < 4; ni++)
                    #pragma unroll
                    for (int cc = 0; cc < 2; cc++) {
                        int jl = wn + ni * 8 + 2 * t + cc;
                        float d2 = si + sjs[jl] - 2.0f * acc[mi][ni][rr * 2 + cc];
                        out[base + (unsigned)(j0 + jl)] = sqrtf(fmaxf(d2, 0.0f));
                    }
            }
    } else {
        #pragma unroll
        for (int mi = 0; mi < 4; mi++)
            #pragma unroll
            for (int rr = 0; rr < 2; rr++) {
                int il = wm + mi * 16 + g + rr * 8;
                int i  = i0 + il;
                float si = sis[il];
                unsigned base = (unsigned)i * (unsigned)(i - 1) / 2u;
                #pragma unroll
                for (int ni = 0; ni < 4; ni++)
                    #pragma unroll
                    for (int cc = 0; cc < 2; cc++) {
                        int jl = wn + ni * 8 + 2 * t + cc;
                        int j  = j0 + jl;
                        if (j < i) {
                            float d2 = si + sjs[jl] - 2.0f * acc[mi][ni][rr * 2 + cc];
                            out[base + (unsigned)j] = sqrtf(fmaxf(d2, 0.0f));
                        }
                    }
            }
    }
}

extern "C" void kernel_launch(void* const* d_in, const int* in_sizes, int n_in,
                              void* d_out, int out_size) {
    const float* x = (const float*)d_in[0];
    float* out = (float*)d_out;

    cudaFuncSetAttribute(pdist_mma_kernel,
                         cudaFuncAttributeMaxDynamicSharedMemorySize, SMEM_BYTES);

    prep_kernel<<<NROWS / 8, 256>>>(x);

    const int nblocks = NT * (NT + 1) / 2;   // 528
    pdist_mma_kernel<<<nblocks, 256, SMEM_BYTES>>>(out);
}

// round 10
// speedup vs baseline: 5.6248x; 1.4272x over previous
#include <cuda_runtime.h>
#include <cuda_bf16.h>
#include <cstdint>
#include <math.h>

#define NROWS 4096
#define DIM   512
#define BMI   128                 // CTA tile rows (i)
#define BNJ   64                  // CTA tile cols (j)
#define BK    64                  // bf16 elements per k-iteration (128 B/row)
#define NTI   (NROWS / BMI)       // 32
#define NITER (DIM / BK)          // 8
#define SPAD  72                  // smem row stride in bf16 (64 + 8 pad)
#define ASTGE (BMI * SPAD)        // 9216 bf16 per A stage
#define BSTGE (BNJ * SPAD)        // 4608 bf16 per B stage

// dynamic smem (bf16): As[2][128][72] | Bs[2][64][72] | sis[128]f32 | sjs[64]f32
#define SMEM_BYTES ((2 * ASTGE + 2 * BSTGE) * 2 + (BMI + BNJ) * 4)

__device__ float g_sq[NROWS];
__device__ __nv_bfloat16 g_xb[NROWS * DIM];   // bf16-rounded copy of x (4 MB)

__device__ __forceinline__ uint32_t smem_u32(const void* p) {
    uint32_t a;
    asm("{ .reg .u64 t; cvta.to.shared.u64 t, %1; cvt.u32.u64 %0, t; }"
        : "=r"(a) : "l"(p));
    return a;
}

__device__ __forceinline__ void mma16816(float* d, const uint32_t* a, const uint32_t* b) {
    asm volatile(
        "mma.sync.aligned.m16n8k16.row.col.f32.bf16.bf16.f32 "
        "{%0,%1,%2,%3}, {%4,%5,%6,%7}, {%8,%9}, {%0,%1,%2,%3};"
        : "+f"(d[0]), "+f"(d[1]), "+f"(d[2]), "+f"(d[3])
        : "r"(a[0]), "r"(a[1]), "r"(a[2]), "r"(a[3]), "r"(b[0]), "r"(b[1]));
}

#define LDSM4(r0, r1, r2, r3, addr)                                             \
    asm volatile("ldmatrix.sync.aligned.m8n8.x4.shared.b16 {%0,%1,%2,%3}, [%4];"\
        : "=r"(r0), "=r"(r1), "=r"(r2), "=r"(r3) : "r"(addr))

// ---------------------------------------------------------------------------
// Kernel 1: bf16-round x into g_xb; fp32 norms of the ROUNDED data.
// ---------------------------------------------------------------------------
__global__ void prep_kernel(const float* __restrict__ x) {
    int row  = blockIdx.x * (blockDim.x >> 5) + (threadIdx.x >> 5);
    int lane = threadIdx.x & 31;
    const float4* xr = (const float4*)(x + (size_t)row * DIM);
    uint2* dr = (uint2*)(g_xb + (size_t)row * DIM);
    float s = 0.0f;
    #pragma unroll
    for (int t = 0; t < 4; t++) {
        float4 v = xr[lane + t * 32];
        __nv_bfloat162 h0 = __floats2bfloat162_rn(v.x, v.y);
        __nv_bfloat162 h1 = __floats2bfloat162_rn(v.z, v.w);
        float a0 = __bfloat162float(h0.x), a1 = __bfloat162float(h0.y);
        float a2 = __bfloat162float(h1.x), a3 = __bfloat162float(h1.y);
        s += a0 * a0 + a1 * a1 + a2 * a2 + a3 * a3;
        uint2 o;
        o.x = *(uint32_t*)&h0; o.y = *(uint32_t*)&h1;
        dr[lane + t * 32] = o;
    }
    #pragma unroll
    for (int o = 16; o > 0; o >>= 1) s += __shfl_xor_sync(0xffffffffu, s, o);
    if (lane == 0) g_sq[row] = s;
}

// ---------------------------------------------------------------------------
// Kernel 2: 128x64 CTA tile, 32x32 warp tiles, bf16 mma.sync, 3 CTAs/SM.
// ---------------------------------------------------------------------------
template <int CHUNKS>
__device__ __forceinline__ void stage_tile(const __nv_bfloat16* __restrict__ src0,
                                           int row0, int k0,
                                           __nv_bfloat16* dst, int tid) {
    #pragma unroll
    for (int h = 0; h < CHUNKS; h++) {
        int e   = tid + h * 256;
        int row = e >> 3;          // 8 x 16B (8 bf16) chunks per 128B row
        int seg = e & 7;
        const __nv_bfloat16* g = src0 + (size_t)(row0 + row) * DIM + k0 + seg * 8;
        uint32_t d = smem_u32(dst + row * SPAD + seg * 8);
        asm volatile("cp.async.cg.shared.global [%0], [%1], 16;"
                     :: "r"(d), "l"(g) : "memory");
    }
}

__global__ __launch_bounds__(256, 3)
void pdist_mma_kernel(float* __restrict__ out) {
    extern __shared__ __nv_bfloat16 smb[];
    __nv_bfloat16* As = smb;
    __nv_bfloat16* Bs = smb + 2 * ASTGE;
    float* sis = (float*)(smb + 2 * ASTGE + 2 * BSTGE);
    float* sjs = sis + BMI;

    const int tid  = threadIdx.x;
    const int wid  = tid >> 5;
    const int lane = tid & 31;
    const int g    = lane >> 2;        // acc row group 0..7
    const int t    = lane & 3;         // acc col group 0..3
    const int wm   = (wid & 3) * 32;   // warp m offset (0/32/64/96)
    const int wn   = (wid >> 2) * 32;  // warp n offset (0/32)

    // block -> (ti, tj): ti over 128-row bands, tj over 64-col bands,
    // tj in [0, 2*ti+2), cumulative offset = ti^2 + ti.
    int bid = blockIdx.x;
    int ti = (int)((sqrtf(4.0f * (float)bid + 1.0f) - 1.0f) * 0.5f);
    if (ti < 0) ti = 0;
    if (ti > NTI - 1) ti = NTI - 1;
    while (ti + 1 < NTI && (ti + 1) * (ti + 2) <= bid) ti++;
    while (ti > 0 && ti * (ti + 1) > bid) ti--;
    int tj = bid - ti * (ti + 1);
    const int i0 = ti * BMI, j0 = tj * BNJ;

    if (tid < BMI) sis[tid] = g_sq[i0 + tid];
    if (tid < BNJ) sjs[tid] = g_sq[j0 + tid];

    // ldmatrix lane addresses
    const uint32_t a_base = smem_u32(
        As + (wm + (((lane >> 3) & 1) << 3) + (lane & 7)) * SPAD + ((lane >> 4) << 3));
    const uint32_t b_base = smem_u32(
        Bs + (wn + ((lane >> 4) << 3) + (lane & 7)) * SPAD + (((lane >> 3) & 1) << 3));

    float acc[2][4][4];
    #pragma unroll
    for (int a = 0; a < 2; a++)
        #pragma unroll
        for (int b = 0; b < 4; b++)
            #pragma unroll
            for (int c = 0; c < 4; c++)
                acc[a][b][c] = 0.0f;

    // prologue: stage 0
    stage_tile<4>(g_xb, i0, 0, As, tid);
    stage_tile<2>(g_xb, j0, 0, Bs, tid);
    asm volatile("cp.async.commit_group;" ::: "memory");

    for (int c = 0; c < NITER; c++) {
        const int s = c & 1;
        asm volatile("cp.async.wait_group 0;" ::: "memory");
        // one barrier: orders last iter's reads of stage s^1 before the
        // prefetch writes below, and makes stage s visible to all warps.
        __syncthreads();
        if (c + 1 < NITER) {
            const int ns = s ^ 1;
            stage_tile<4>(g_xb, i0, (c + 1) * BK, As + ns * ASTGE, tid);
            stage_tile<2>(g_xb, j0, (c + 1) * BK, Bs + ns * BSTGE, tid);
            asm volatile("cp.async.commit_group;" ::: "memory");
        }

        const uint32_t aoff = (uint32_t)(s * ASTGE * 2);
        const uint32_t boff = (uint32_t)(s * BSTGE * 2);
        #pragma unroll
        for (int ks = 0; ks < 4; ks++) {
            const uint32_t ko = (uint32_t)(ks * 32);   // +16 bf16
            uint32_t bregs[2][4];
            LDSM4(bregs[0][0], bregs[0][1], bregs[0][2], bregs[0][3],
                  b_base + boff + ko);
            LDSM4(bregs[1][0], bregs[1][1], bregs[1][2], bregs[1][3],
                  b_base + boff + ko + 16 * SPAD * 2);
            #pragma unroll
            for (int mi = 0; mi < 2; mi++) {
                uint32_t af[4];
                LDSM4(af[0], af[1], af[2], af[3],
                      a_base + aoff + ko + (uint32_t)(mi * 16 * SPAD * 2));
                mma16816(acc[mi][0], af, &bregs[0][0]);
                mma16816(acc[mi][1], af, &bregs[0][2]);
                mma16816(acc[mi][2], af, &bregs[1][0]);
                mma16816(acc[mi][3], af, &bregs[1][2]);
            }
        }
    }

    // epilogue: d = sqrt(max(si + sj - 2*dot, 0)) at out[i*(i-1)/2 + j], i > j
    // full tiles: j0 + 63 < i0  <=>  tj < 2*ti
    if (tj < 2 * ti) {
        #pragma unroll
        for (int mi = 0; mi < 2; mi++)
            #pragma unroll
            for (int rr = 0; rr < 2; rr++) {
                int il = wm + mi * 16 + g + rr * 8;
                int i  = i0 + il;
                float si = sis[il];
                unsigned base = (unsigned)i * (unsigned)(i - 1) / 2u;
                #pragma unroll
                for (int ni = 0; ni < 4; ni++)
                    #pragma unroll
                    for (int cc = 0; cc < 2; cc++) {
                        int jl = wn + ni * 8 + 2 * t + cc;
                        float d2 = si + sjs[jl] - 2.0f * acc[mi][ni][rr * 2 + cc];
                        out[base + (unsigned)(j0 + jl)] = sqrtf(fmaxf(d2, 0.0f));
                    }
            }
    } else {
        #pragma unroll
        for (int mi = 0; mi < 2; mi++)
            #pragma unroll
            for (int rr = 0; rr < 2; rr++) {
                int il = wm + mi * 16 + g + rr * 8;
                int i  = i0 + il;
                float si = sis[il];
                unsigned base = (unsigned)i * (unsigned)(i - 1) / 2u;
                #pragma unroll
                for (int ni = 0; ni < 4; ni++)
                    #pragma unroll
                    for (int cc = 0; cc < 2; cc++) {
                        int jl = wn + ni * 8 + 2 * t + cc;
                        int j  = j0 + jl;
                        if (j < i) {
                            float d2 = si + sjs[jl] - 2.0f * acc[mi][ni][rr * 2 + cc];
                            out[base + (unsigned)j] = sqrtf(fmaxf(d2, 0.0f));
                        }
                    }
            }
    }
}

extern "C" void kernel_launch(void* const* d_in, const int* in_sizes, int n_in,
                              void* d_out, int out_size) {
    const float* x = (const float*)d_in[0];
    float* out = (float*)d_out;

    cudaFuncSetAttribute(pdist_mma_kernel,
                         cudaFuncAttributeMaxDynamicSharedMemorySize, SMEM_BYTES);

    prep_kernel<<<NROWS / 8, 256>>>(x);

    const int nblocks = NTI * NTI + NTI;   // sum over ti of (2*ti + 2) = 1056
    pdist_mma_kernel<<<nblocks, 256, SMEM_BYTES>>>(out);
}

// round 11
// speedup vs baseline: 6.0751x; 1.0801x over previous
#include <cuda_runtime.h>
#include <cuda_bf16.h>
#include <cstdint>
#include <math.h>

#define NROWS 4096
#define DIM   512
#define BMI   128                 // CTA tile rows (i)
#define BNJ   64                  // CTA tile cols (j)
#define BK    64                  // bf16 elements per k-iteration (128 B/row)
#define NTI   (NROWS / BMI)       // 32
#define NITER (DIM / BK)          // 8
#define SPAD  72                  // smem row stride in bf16 (64 + 8 pad)
#define ASTGE (BMI * SPAD)        // 9216 bf16 per A stage
#define BSTGE (BNJ * SPAD)        // 4608 bf16 per B stage

// dynamic smem (bf16): As[2][128][72] | Bs[2][64][72] | sis[128]f32 | sjs[64]f32
#define SMEM_BYTES ((2 * ASTGE + 2 * BSTGE) * 2 + (BMI + BNJ) * 4)

__device__ float g_sq[NROWS];
__device__ __nv_bfloat16 g_xb[NROWS * DIM];   // bf16-rounded copy of x (4 MB)

__device__ __forceinline__ uint32_t smem_u32(const void* p) {
    uint32_t a;
    asm("{ .reg .u64 t; cvta.to.shared.u64 t, %1; cvt.u32.u64 %0, t; }"
        : "=r"(a) : "l"(p));
    return a;
}

__device__ __forceinline__ void mma16816(float* d, const uint32_t* a, const uint32_t* b) {
    asm volatile(
        "mma.sync.aligned.m16n8k16.row.col.f32.bf16.bf16.f32 "
        "{%0,%1,%2,%3}, {%4,%5,%6,%7}, {%8,%9}, {%0,%1,%2,%3};"
        : "+f"(d[0]), "+f"(d[1]), "+f"(d[2]), "+f"(d[3])
        : "r"(a[0]), "r"(a[1]), "r"(a[2]), "r"(a[3]), "r"(b[0]), "r"(b[1]));
}

#define LDSM4(r0, r1, r2, r3, addr)                                             \
    asm volatile("ldmatrix.sync.aligned.m8n8.x4.shared.b16 {%0,%1,%2,%3}, [%4];"\
        : "=r"(r0), "=r"(r1), "=r"(r2), "=r"(r3) : "r"(addr))

// ---------------------------------------------------------------------------
// Kernel 1: bf16-round x into g_xb; fp32 norms of the ROUNDED data.
// ---------------------------------------------------------------------------
__global__ void prep_kernel(const float* __restrict__ x) {
    int row  = blockIdx.x * (blockDim.x >> 5) + (threadIdx.x >> 5);
    int lane = threadIdx.x & 31;
    const float4* xr = (const float4*)(x + (size_t)row * DIM);
    uint2* dr = (uint2*)(g_xb + (size_t)row * DIM);
    float s = 0.0f;
    #pragma unroll
    for (int t = 0; t < 4; t++) {
        float4 v = xr[lane + t * 32];
        __nv_bfloat162 h0 = __floats2bfloat162_rn(v.x, v.y);
        __nv_bfloat162 h1 = __floats2bfloat162_rn(v.z, v.w);
        float a0 = __bfloat162float(h0.x), a1 = __bfloat162float(h0.y);
        float a2 = __bfloat162float(h1.x), a3 = __bfloat162float(h1.y);
        s += a0 * a0 + a1 * a1 + a2 * a2 + a3 * a3;
        uint2 o;
        o.x = *(uint32_t*)&h0; o.y = *(uint32_t*)&h1;
        dr[lane + t * 32] = o;
    }
    #pragma unroll
    for (int o = 16; o > 0; o >>= 1) s += __shfl_xor_sync(0xffffffffu, s, o);
    if (lane == 0) g_sq[row] = s;
}

// ---------------------------------------------------------------------------
// Kernel 2: 128x64 CTA tile, 32x32 warp tiles, bf16 mma.sync, 4 CTAs/SM.
// ---------------------------------------------------------------------------
template <int CHUNKS>
__device__ __forceinline__ void stage_tile(const __nv_bfloat16* __restrict__ src0,
                                           int row0, int k0,
                                           __nv_bfloat16* dst, int tid) {
    #pragma unroll
    for (int h = 0; h < CHUNKS; h++) {
        int e   = tid + h * 256;
        int row = e >> 3;          // 8 x 16B (8 bf16) chunks per 128B row
        int seg = e & 7;
        const __nv_bfloat16* g = src0 + (size_t)(row0 + row) * DIM + k0 + seg * 8;
        uint32_t d = smem_u32(dst + row * SPAD + seg * 8);
        asm volatile("cp.async.cg.shared.global [%0], [%1], 16;"
                     :: "r"(d), "l"(g) : "memory");
    }
}

__global__ __launch_bounds__(256, 4)
void pdist_mma_kernel(float* __restrict__ out) {
    extern __shared__ __nv_bfloat16 smb[];
    __nv_bfloat16* As = smb;
    __nv_bfloat16* Bs = smb + 2 * ASTGE;
    float* sis = (float*)(smb + 2 * ASTGE + 2 * BSTGE);
    float* sjs = sis + BMI;

    const int tid  = threadIdx.x;
    const int wid  = tid >> 5;
    const int lane = tid & 31;
    const int g    = lane >> 2;        // acc row group 0..7
    const int t    = lane & 3;         // acc col group 0..3
    const int wm   = (wid & 3) * 32;   // warp m offset (0/32/64/96)
    const int wn   = (wid >> 2) * 32;  // warp n offset (0/32)

    // block -> (ti, tj): ti over 128-row bands, tj over 64-col bands,
    // tj in [0, 2*ti+2), cumulative offset = ti^2 + ti.
    int bid = blockIdx.x;
    int ti = (int)((sqrtf(4.0f * (float)bid + 1.0f) - 1.0f) * 0.5f);
    if (ti < 0) ti = 0;
    if (ti > NTI - 1) ti = NTI - 1;
    while (ti + 1 < NTI && (ti + 1) * (ti + 2) <= bid) ti++;
    while (ti > 0 && ti * (ti + 1) > bid) ti--;
    int tj = bid - ti * (ti + 1);
    const int i0 = ti * BMI, j0 = tj * BNJ;

    if (tid < BMI) sis[tid] = g_sq[i0 + tid];
    if (tid < BNJ) sjs[tid] = g_sq[j0 + tid];

    // ldmatrix lane addresses
    const uint32_t a_base = smem_u32(
        As + (wm + (((lane >> 3) & 1) << 3) + (lane & 7)) * SPAD + ((lane >> 4) << 3));
    const uint32_t b_base = smem_u32(
        Bs + (wn + ((lane >> 4) << 3) + (lane & 7)) * SPAD + (((lane >> 3) & 1) << 3));

    float acc[2][4][4];
    #pragma unroll
    for (int a = 0; a < 2; a++)
        #pragma unroll
        for (int b = 0; b < 4; b++)
            #pragma unroll
            for (int c = 0; c < 4; c++)
                acc[a][b][c] = 0.0f;

    // prologue: stage 0
    stage_tile<4>(g_xb, i0, 0, As, tid);
    stage_tile<2>(g_xb, j0, 0, Bs, tid);
    asm volatile("cp.async.commit_group;" ::: "memory");

    for (int c = 0; c < NITER; c++) {
        const int s = c & 1;
        asm volatile("cp.async.wait_group 0;" ::: "memory");
        // one barrier: orders last iter's reads of stage s^1 before the
        // prefetch writes below, and makes stage s visible to all warps.
        __syncthreads();
        if (c + 1 < NITER) {
            const int ns = s ^ 1;
            stage_tile<4>(g_xb, i0, (c + 1) * BK, As + ns * ASTGE, tid);
            stage_tile<2>(g_xb, j0, (c + 1) * BK, Bs + ns * BSTGE, tid);
            asm volatile("cp.async.commit_group;" ::: "memory");
        }

        const uint32_t ab = a_base + (uint32_t)(s * ASTGE * 2);
        const uint32_t bb = b_base + (uint32_t)(s * BSTGE * 2);
        #pragma unroll
        for (int ks = 0; ks < 4; ks++) {
            const uint32_t ko = (uint32_t)(ks * 32);   // +16 bf16
            uint32_t bregs[2][4];
            LDSM4(bregs[0][0], bregs[0][1], bregs[0][2], bregs[0][3], bb + ko);
            LDSM4(bregs[1][0], bregs[1][1], bregs[1][2], bregs[1][3],
                  bb + ko + 16 * SPAD * 2);
            #pragma unroll
            for (int mi = 0; mi < 2; mi++) {
                uint32_t af[4];
                LDSM4(af[0], af[1], af[2], af[3],
                      ab + ko + (uint32_t)(mi * 16 * SPAD * 2));
                mma16816(acc[mi][0], af, &bregs[0][0]);
                mma16816(acc[mi][1], af, &bregs[0][2]);
                mma16816(acc[mi][2], af, &bregs[1][0]);
                mma16816(acc[mi][3], af, &bregs[1][2]);
            }
        }
    }

    // epilogue: d = sqrt(max(si + sj - 2*dot, 0)) at out[i*(i-1)/2 + j], i > j
    // full tiles: j0 + 63 < i0  <=>  tj < 2*ti
    if (tj < 2 * ti) {
        #pragma unroll
        for (int mi = 0; mi < 2; mi++)
            #pragma unroll
            for (int rr = 0; rr < 2; rr++) {
                int il = wm + mi * 16 + g + rr * 8;
                int i  = i0 + il;
                float si = sis[il];
                unsigned base = (unsigned)i * (unsigned)(i - 1) / 2u;
                #pragma unroll
                for (int ni = 0; ni < 4; ni++)
                    #pragma unroll
                    for (int cc = 0; cc < 2; cc++) {
                        int jl = wn + ni * 8 + 2 * t + cc;
                        float d2 = si + sjs[jl] - 2.0f * acc[mi][ni][rr * 2 + cc];
                        out[base + (unsigned)(j0 + jl)] = sqrtf(fmaxf(d2, 0.0f));
                    }
            }
    } else {
        #pragma unroll
        for (int mi = 0; mi < 2; mi++)
            #pragma unroll
            for (int rr = 0; rr < 2; rr++) {
                int il = wm + mi * 16 + g + rr * 8;
                int i  = i0 + il;
                float si = sis[il];
                unsigned base = (unsigned)i * (unsigned)(i - 1) / 2u;
                #pragma unroll
                for (int ni = 0; ni < 4; ni++)
                    #pragma unroll
                    for (int cc = 0; cc < 2; cc++) {
                        int jl = wn + ni * 8 + 2 * t + cc;
                        int j  = j0 + jl;
                        if (j < i) {
                            float d2 = si + sjs[jl] - 2.0f * acc[mi][ni][rr * 2 + cc];
                            out[base + (unsigned)j] = sqrtf(fmaxf(d2, 0.0f));
                        }
                    }
            }
    }
}

extern "C" void kernel_launch(void* const* d_in, const int* in_sizes, int n_in,
                              void* d_out, int out_size) {
    const float* x = (const float*)d_in[0];
    float* out = (float*)d_out;

    cudaFuncSetAttribute(pdist_mma_kernel,
                         cudaFuncAttributeMaxDynamicSharedMemorySize, SMEM_BYTES);

    prep_kernel<<<NROWS / 8, 256>>>(x);

    const int nblocks = NTI * NTI + NTI;   // sum over ti of (2*ti + 2) = 1056
    pdist_mma_kernel<<<nblocks, 256, SMEM_BYTES>>>(out);
}